// round 13
// baseline (speedup 1.0000x reference)
#include <cuda_runtime.h>
#include <math.h>
#include <stdint.h>

#define TT 48
#define BB 16
#define EE 512
#define VV 50000
#define SS 40000
#define GG 32
#define KK 8
#define NC 20
#define ROWS (TT*BB)          // 768
#define N4  (VV/4)            // 12500
#define CAP 1024              // candidate buffer capacity
#define T0  3.0f              // filter threshold (exact fallback if <8 pass)
#define BD  4                 // load batch depth
#define BATCH (512*BD)        // 2048 float4 per batch
#define NFULL ((N4/BATCH)*BATCH)   // 12288
#define QSS (SS/4)            // 10000 floats per quarter-row fill

// ---- scratch (no allocations allowed) ----
__device__ int g_topk[ROWS * KK];
__device__ unsigned long long g_best[ROWS];

__device__ __forceinline__ bool better(float v1, int i1, float v2, int i2) {
    return (v1 > v2) || (v1 == v2 && i1 < i2);
}

__device__ __forceinline__ uint32_t fkey(float f) {
    uint32_t u = __float_as_uint(f);
    return (u & 0x80000000u) ? ~u : (u | 0x80000000u);   // order-preserving
}

__device__ __forceinline__ void insert8(float tv[8], int ti[8], float cv, int ci) {
#pragma unroll
    for (int j = 0; j < 8; j++) {
        if (better(cv, ci, tv[j], ti[j])) {
            float fv = tv[j]; int iv = ti[j];
            tv[j] = cv; ti[j] = ci;
            cv = fv; ci = iv;
        }
    }
}

__device__ __forceinline__ void warp_merge8(float tv[8], int ti[8], int off) {
    float pv[8]; int pi[8];
#pragma unroll
    for (int j = 0; j < 8; j++) {
        pv[j] = __shfl_xor_sync(0xffffffffu, tv[7 - j], off);
        pi[j] = __shfl_xor_sync(0xffffffffu, ti[7 - j], off);
    }
#pragma unroll
    for (int j = 0; j < 8; j++) {
        if (better(pv[j], pi[j], tv[j], ti[j])) { tv[j] = pv[j]; ti[j] = pi[j]; }
    }
    auto ce = [&](int p, int q) {
        if (better(tv[q], ti[q], tv[p], ti[p])) {
            float fv = tv[p]; tv[p] = tv[q]; tv[q] = fv;
            int iv = ti[p]; ti[p] = ti[q]; ti[q] = iv;
        }
    };
    ce(0,4); ce(1,5); ce(2,6); ce(3,7);
    ce(0,2); ce(1,3); ce(4,6); ce(5,7);
    ce(0,1); ce(2,3); ce(4,5); ce(6,7);
}

// ============================================================================
// Kernel B: softmax + topk (+ g_best init). Unchanged (66.5us measured).
// ============================================================================
__global__ __launch_bounds__(512, 3)
void softmax_topk_kernel(const float* __restrict__ logits,
                         float* __restrict__ out_globals)
{
    __shared__ float s_cval[CAP];
    __shared__ int   s_cidx[CAP];
    __shared__ int   s_cnt;
    __shared__ float s_wtv[128];
    __shared__ int   s_wti[128];
    __shared__ float s_ws[16];
    __shared__ float s_lse;

    const int row = blockIdx.x;
    const int tid = threadIdx.x;
    const int lane = tid & 31;
    const int wid = tid >> 5;   // 16 warps

    const float4* in4 = (const float4*)(logits + (size_t)row * VV);

    if (tid == 0) { s_cnt = 0; g_best[row] = 0ull; }
    __syncthreads();

    float acc[BD];
#pragma unroll
    for (int u = 0; u < BD; u++) acc[u] = 0.f;

#pragma unroll 1
    for (int base = 0; base + BATCH <= N4; base += BATCH) {
        float4 q[BD];
#pragma unroll
        for (int u = 0; u < BD; u++) q[u] = __ldcg(&in4[base + u * 512 + tid]);
#pragma unroll
        for (int u = 0; u < BD; u++) {
            acc[u] += __expf(q[u].x) + __expf(q[u].y) + __expf(q[u].z) + __expf(q[u].w);
            float q4m = fmaxf(fmaxf(q[u].x, q[u].y), fmaxf(q[u].z, q[u].w));
            if (__any_sync(0xffffffffu, q4m > T0)) {        // rare slow path
                if (q4m > T0) {
                    const int gbase = 4 * (base + u * 512 + tid);
                    float vals[4] = { q[u].x, q[u].y, q[u].z, q[u].w };
#pragma unroll
                    for (int k = 0; k < 4; k++) {
                        if (vals[k] > T0) {
                            int slot = atomicAdd(&s_cnt, 1);
                            if (slot < CAP) { s_cval[slot] = vals[k]; s_cidx[slot] = gbase + k; }
                        }
                    }
                }
            }
        }
    }
    {
        int i = NFULL + tid;
        if (i < N4) {
            float4 q = __ldcg(&in4[i]);
            acc[0] += __expf(q.x) + __expf(q.y) + __expf(q.z) + __expf(q.w);
            float vals[4] = { q.x, q.y, q.z, q.w };
#pragma unroll
            for (int k = 0; k < 4; k++) {
                if (vals[k] > T0) {
                    int slot = atomicAdd(&s_cnt, 1);
                    if (slot < CAP) { s_cval[slot] = vals[k]; s_cidx[slot] = 4 * i + k; }
                }
            }
        }
    }

    float s = 0.f;
#pragma unroll
    for (int u = 0; u < BD; u++) s += acc[u];
#pragma unroll
    for (int off = 16; off; off >>= 1)
        s += __shfl_xor_sync(0xffffffffu, s, off);
    if (lane == 0) s_ws[wid] = s;
    __syncthreads();

    const int cnt = s_cnt;
    if (cnt >= 8 && cnt <= CAP) {
        if (wid == 0) {
            float tv[8]; int ti[8];
#pragma unroll
            for (int j = 0; j < 8; j++) { tv[j] = -INFINITY; ti[j] = 0x7fffffff; }
            for (int i = lane; i < cnt; i += 32) insert8(tv, ti, s_cval[i], s_cidx[i]);
#pragma unroll
            for (int off = 1; off < 32; off <<= 1) warp_merge8(tv, ti, off);
            if (lane == 0) {
#pragma unroll
                for (int j = 0; j < 8; j++) g_topk[row * KK + j] = ti[j];
            }
        }
    } else {
        // exact fallback: full rescan with per-thread top-8
        float tv[8]; int ti[8];
#pragma unroll
        for (int j = 0; j < 8; j++) { tv[j] = -INFINITY; ti[j] = 0x7fffffff; }
        for (int i = tid; i < N4; i += 512) {
            float4 q = in4[i];
            float vals[4] = { q.x, q.y, q.z, q.w };
#pragma unroll
            for (int k = 0; k < 4; k++)
                if (better(vals[k], 4 * i + k, tv[7], ti[7])) insert8(tv, ti, vals[k], 4 * i + k);
        }
#pragma unroll
        for (int off = 1; off < 32; off <<= 1) warp_merge8(tv, ti, off);
        if (lane == 0) {
#pragma unroll
            for (int j = 0; j < 8; j++) { s_wtv[wid * 8 + j] = tv[j]; s_wti[wid * 8 + j] = ti[j]; }
        }
        __syncthreads();
        if (wid == 0) {
            float fv[8]; int fi[8];
            if (lane < 16) {
#pragma unroll
                for (int j = 0; j < 8; j++) { fv[j] = s_wtv[lane * 8 + j]; fi[j] = s_wti[lane * 8 + j]; }
            } else {
#pragma unroll
                for (int j = 0; j < 8; j++) { fv[j] = -INFINITY; fi[j] = 0x7fffffff; }
            }
#pragma unroll
            for (int off = 1; off < 16; off <<= 1) warp_merge8(fv, fi, off);
            if (lane == 0) {
#pragma unroll
                for (int j = 0; j < 8; j++) g_topk[row * KK + j] = fi[j];
            }
        }
    }

    if (tid == 0) {
        float S = s_ws[0];
#pragma unroll
        for (int w = 1; w < 16; w++) S += s_ws[w];
        s_lse = logf(S);
    }
    __syncthreads();
    const float lse = s_lse;

    float4* o4 = (float4*)(out_globals + (size_t)row * VV);
#pragma unroll 1
    for (int base = 0; base + BATCH <= N4; base += BATCH) {
        float4 q[BD];
#pragma unroll
        for (int u = 0; u < BD; u++) q[u] = __ldcs(&in4[base + u * 512 + tid]);
#pragma unroll
        for (int u = 0; u < BD; u++) {
            q[u].x -= lse; q[u].y -= lse; q[u].z -= lse; q[u].w -= lse;
            __stcs(&o4[base + u * 512 + tid], q[u]);
        }
    }
    {
        int i = NFULL + tid;
        if (i < N4) {
            float4 q = __ldcs(&in4[i]);
            q.x -= lse; q.y -= lse; q.z -= lse; q.w -= lse;
            __stcs(&o4[i], q);
        }
    }
}

// ============================================================================
// Kernel D: 4 CTAs per row, 64 candidates each (8 warps x 8). Structure that
// passed twice (R9 shape, 2x verified); one change: the quarter-row senses
// fill is issued FIRST (fire-and-forget stores drain during the loc-context
// loads and SC gathers instead of serializing after them).
// Cross-CTA argmax combine via atomicMax on order-preserving 64-bit key.
// ============================================================================
__global__ __launch_bounds__(256, 4)
void sense_argmax_kernel(const float* __restrict__ word,
                         const float* __restrict__ prev,
                         const float* __restrict__ locin,
                         const float* __restrict__ SC,
                         const int*   __restrict__ neigh,
                         float* __restrict__ out_senses,
                         float log_eps)
{
    __shared__ float s_loc[EE];
    __shared__ int   s_tk[KK];
    __shared__ unsigned long long s_bk[8];

    const int row = blockIdx.x >> 2;
    const int qtr = blockIdx.x & 3;
    const int t = row / BB, b = row % BB;
    const int tid = threadIdx.x;

    // ---- fill FIRST: stores issue now, drain in background of everything ----
    {
        float4* so4 = (float4*)(out_senses + (size_t)row * SS + qtr * QSS);
        const float4 qe = { log_eps, log_eps, log_eps, log_eps };
#pragma unroll
        for (int i = 0; i < QSS / 4 / 256 + 1; i++) {
            int idx = i * 256 + tid;
            if (idx < QSS / 4) __stcs(&so4[idx], qe);
        }
    }

    // ---- loc context ----
#pragma unroll
    for (int hh = 0; hh < 2; hh++) {
        int e = tid + hh * 256;
        float acc = 0.0f;
#pragma unroll
        for (int j = 0; j < NC; j++) {
            int cj = t + TT - NC + 1 + j;    // t+29 .. t+48
            const float* src = (cj < TT) ? prev : word;
            int r = (cj < TT) ? cj : (cj - TT);
            acc += src[((size_t)r * BB + b) * EE + e];
        }
        s_loc[e] = locin[(size_t)row * EE + e] + acc * (1.0f / NC);
    }
    if (tid < KK) s_tk[tid] = g_topk[row * KK + tid];
    __syncthreads();

    const int wid = tid >> 5, lane = tid & 31;
    const float4* loc4 = (const float4*)s_loc;

    const int cbase = qtr * 64 + wid * 8;             // this warp's 8 candidates
    const int tkw   = s_tk[cbase >> 5];
    const int* nptr = neigh + (size_t)tkw * GG + (cbase & 31);

    unsigned long long bestk = 0ull;
#pragma unroll 1
    for (int it = 0; it < 2; it++) {
        int sid[4];
#pragma unroll
        for (int j = 0; j < 4; j++) sid[j] = nptr[it * 4 + j];
        const float4* bp[4];
#pragma unroll
        for (int j = 0; j < 4; j++) bp[j] = (const float4*)(SC + (size_t)sid[j] * EE);

        float d[4] = {0.f,0.f,0.f,0.f}, n[4] = {0.f,0.f,0.f,0.f};
#pragma unroll
        for (int u = 0; u < 4; u++) {
            float4 aq = loc4[u * 32 + lane];
            float4 qv[4];
#pragma unroll
            for (int j = 0; j < 4; j++) qv[j] = bp[j][u * 32 + lane];
#pragma unroll
            for (int j = 0; j < 4; j++) {       // identical order for all j
                d[j] = fmaf(aq.x, qv[j].x, d[j]);
                d[j] = fmaf(aq.y, qv[j].y, d[j]);
                d[j] = fmaf(aq.z, qv[j].z, d[j]);
                d[j] = fmaf(aq.w, qv[j].w, d[j]);
                n[j] = fmaf(qv[j].x, qv[j].x, n[j]);
                n[j] = fmaf(qv[j].y, qv[j].y, n[j]);
                n[j] = fmaf(qv[j].z, qv[j].z, n[j]);
                n[j] = fmaf(qv[j].w, qv[j].w, n[j]);
            }
        }
#pragma unroll
        for (int off = 16; off; off >>= 1) {
#pragma unroll
            for (int j = 0; j < 4; j++) {
                d[j] += __shfl_xor_sync(0xffffffffu, d[j], off);
                n[j] += __shfl_xor_sync(0xffffffffu, n[j], off);
            }
        }
#pragma unroll
        for (int j = 0; j < 4; j++) {
            float score = d[j] / fmaxf(sqrtf(n[j]), 1e-8f);
            unsigned int c = cbase + it * 4 + j;
            unsigned long long key =
                ((unsigned long long)fkey(score) << 32) | (0xFFFFFFFFu - c);
            if (key > bestk) bestk = key;
        }
    }
    if (lane == 0) s_bk[wid] = bestk;
    __syncthreads();
    if (tid == 0) {
        unsigned long long k = s_bk[0];
#pragma unroll
        for (int w = 1; w < 8; w++) if (s_bk[w] > k) k = s_bk[w];
        atomicMax(&g_best[row], k);
    }
}

// ============================================================================
// Kernel E: decode winners, write log_chosen (fills done by kernel D).
// ============================================================================
__global__ void scatter_chosen_kernel(const int* __restrict__ neigh,
                                      float* __restrict__ out_senses,
                                      float log_chosen)
{
    int row = threadIdx.x;   // 768 threads, one block
    if (row < ROWS) {
        unsigned long long key = g_best[row];
        unsigned int c = 0xFFFFFFFFu - (unsigned int)(key & 0xFFFFFFFFu);
        int tk = g_topk[row * KK + (c >> 5)];
        int chosen = neigh[(size_t)tk * GG + (c & 31)];
        out_senses[(size_t)row * SS + chosen] = log_chosen;
    }
}

// ============================================================================
extern "C" void kernel_launch(void* const* d_in, const int* in_sizes, int n_in,
                              void* d_out, int out_size)
{
    (void)in_sizes; (void)n_in; (void)out_size;
    const float* word   = (const float*)d_in[0];
    const float* prev   = (const float*)d_in[1];
    const float* locc   = (const float*)d_in[2];
    const float* logits = (const float*)d_in[3];
    const float* SC     = (const float*)d_in[4];
    const int*   neigh  = (const int*)d_in[5];

    float* out_globals = (float*)d_out;
    float* out_senses  = out_globals + (size_t)ROWS * VV;

    const float log_eps    = logf(1e-8f);
    const float log_chosen = logf((float)(1.0 - 1e-8 * (double)(SS - 1)));

    softmax_topk_kernel<<<ROWS, 512>>>(logits, out_globals);
    sense_argmax_kernel<<<ROWS * 4, 256>>>(word, prev, locc, SC, neigh,
                                           out_senses, log_eps);
    scatter_chosen_kernel<<<1, ROWS>>>(neigh, out_senses, log_chosen);
}